// round 3
// baseline (speedup 1.0000x reference)
#include <cuda_runtime.h>
#include <cstdint>

#define S_LEN   2048
#define D_K     64
#define BH      64
#define MT      64
#define NT      64
#define PADK    68          // stride%32banks = 4 -> conflict-free K/P gathers
#define PADV    72          // stride%32banks = 8 -> conflict-free V B-operand gathers
#define THREADS 256

__device__ __forceinline__ uint32_t f2tf32(float x) {
    uint32_t r;
    asm("cvt.rna.tf32.f32 %0, %1;" : "=r"(r) : "f"(x));
    return r;
}

__device__ __forceinline__ void mma_tf32(float c[4],
                                         uint32_t a0, uint32_t a1, uint32_t a2, uint32_t a3,
                                         uint32_t b0, uint32_t b1) {
    asm volatile(
        "mma.sync.aligned.m16n8k8.row.col.f32.tf32.tf32.f32 "
        "{%0,%1,%2,%3},{%4,%5,%6,%7},{%8,%9},{%0,%1,%2,%3};"
        : "+f"(c[0]), "+f"(c[1]), "+f"(c[2]), "+f"(c[3])
        : "r"(a0), "r"(a1), "r"(a2), "r"(a3), "r"(b0), "r"(b1));
}

__device__ __forceinline__ void cp_async16(uint32_t s, const void* g) {
    asm volatile("cp.async.cg.shared.global [%0], [%1], 16;" :: "r"(s), "l"(g));
}
#define CP_COMMIT() asm volatile("cp.async.commit_group;")
#define CP_WAIT1()  asm volatile("cp.async.wait_group 1;")
#define CP_WAIT0()  asm volatile("cp.async.wait_group 0;")

// issue cp.asyncs for one 64x64 fp32 tile (raw) into padded smem
__device__ __forceinline__ void cp_tile(uint32_t dst_base, const float* __restrict__ src,
                                        int tid, int pad) {
    #pragma unroll
    for (int i = 0; i < 4; i++) {
        int idx = i * THREADS + tid;
        int row = idx >> 4;
        int c4  = (idx & 15) << 2;
        cp_async16(dst_base + (row * pad + c4) * 4, src + idx * 4);
    }
}

__global__ __launch_bounds__(THREADS, 2)
void sdpa_fwd(const float* __restrict__ Q, const float* __restrict__ K,
              const float* __restrict__ V, const int* __restrict__ mask,
              float* __restrict__ out) {
    extern __shared__ float sm[];
    float* Ks[2] = { sm,               sm + NT * PADK };
    float* Vs[2] = { sm + 2 * NT * PADK, sm + 2 * NT * PADK + NT * PADV };
    float* Ps   = sm + 2 * NT * PADK + 2 * NT * PADV;   // MT x PADK
    float* red  = Ps + MT * PADK;                        // 64 x 4
    float* liS  = red + 64 * 4;                          // 64

    const uint32_t smem_u32 = (uint32_t)__cvta_generic_to_shared(sm);
    const uint32_t KsA[2] = { smem_u32, smem_u32 + NT * PADK * 4 };
    const uint32_t VsA[2] = { smem_u32 + 2 * NT * PADK * 4,
                              smem_u32 + 2 * NT * PADK * 4 + NT * PADV * 4 };

    const int bh  = blockIdx.y;
    const int q0  = blockIdx.x * MT;
    const int tid = threadIdx.x;
    const int lane = tid & 31, wid = tid >> 5;
    const int g = lane >> 2, tig = lane & 3;
    const int wm = wid & 1;              // 2 warps in M
    const int wn = wid >> 1;             // 4 warps in N

    const float* Qg = Q + ((size_t)bh * S_LEN + q0) * D_K;
    const float* Kg = K + (size_t)bh * S_LEN * D_K;
    const float* Vg = V + (size_t)bh * S_LEN * D_K;
    const int*   Mg = mask + (size_t)bh * S_LEN * S_LEN;
    float* ctx  = out + (size_t)bh * S_LEN * D_K;
    float* attn = out + (size_t)BH * S_LEN * D_K + (size_t)bh * S_LEN * S_LEN;

    // ---- Q fragments in registers (scale 1/8 folded, tf32) ----
    uint32_t qf[8][2][4];
    #pragma unroll
    for (int j = 0; j < 8; j++) {
        #pragma unroll
        for (int mb = 0; mb < 2; mb++) {
            int r0 = wm * 32 + mb * 16 + g;
            const float* p0 = Qg + (size_t)r0 * D_K + j * 8;
            const float* p1 = Qg + (size_t)(r0 + 8) * D_K + j * 8;
            qf[j][mb][0] = f2tf32(p0[tig]     * 0.125f);
            qf[j][mb][1] = f2tf32(p1[tig]     * 0.125f);
            qf[j][mb][2] = f2tf32(p0[tig + 4] * 0.125f);
            qf[j][mb][3] = f2tf32(p1[tig + 4] * 0.125f);
        }
    }

    // prefetch tile 0 into buffer 0
    cp_tile(KsA[0], Kg, tid, PADK);
    cp_tile(VsA[0], Vg, tid, PADV);
    CP_COMMIT();

    float o[2][2][4] = {};
    float lp[2][2] = {};

    int buf = 0;
    for (int kt = 0; kt < S_LEN; kt += NT, buf ^= 1) {
        __syncthreads();                 // prev tile's smem consumers done (incl. Ps)
        if (kt + NT < S_LEN) {
            cp_tile(KsA[buf ^ 1], Kg + (size_t)(kt + NT) * D_K, tid, PADK);
            cp_tile(VsA[buf ^ 1], Vg + (size_t)(kt + NT) * D_K, tid, PADV);
            CP_COMMIT();
            CP_WAIT1();                  // current tile's group done
        } else {
            CP_WAIT0();
        }
        __syncthreads();                 // all threads' copies visible

        const float* Kc = Ks[buf];
        const float* Vc = Vs[buf];

        // ---- mask prefetch (overlaps with QK mma) ----
        int2 mreg[2][2][2];
        #pragma unroll
        for (int mb = 0; mb < 2; mb++) {
            int row = wm * 32 + mb * 16 + g;
            #pragma unroll
            for (int nf = 0; nf < 2; nf++) {
                int col = wn * 16 + nf * 8 + 2 * tig;
                mreg[mb][nf][0] = *(const int2*)(Mg + (size_t)(q0 + row)     * S_LEN + kt + col);
                mreg[mb][nf][1] = *(const int2*)(Mg + (size_t)(q0 + row + 8) * S_LEN + kt + col);
            }
        }

        // ---- S = Q K^T ----
        float acc[2][2][4] = {};
        #pragma unroll
        for (int j = 0; j < 8; j++) {
            int k0 = j * 8;
            uint32_t b0[2], b1[2];
            #pragma unroll
            for (int nf = 0; nf < 2; nf++) {
                int nc = wn * 16 + nf * 8 + g;
                b0[nf] = f2tf32(Kc[nc * PADK + k0 + tig]);
                b1[nf] = f2tf32(Kc[nc * PADK + k0 + tig + 4]);
            }
            #pragma unroll
            for (int mb = 0; mb < 2; mb++)
                #pragma unroll
                for (int nf = 0; nf < 2; nf++)
                    mma_tf32(acc[mb][nf], qf[j][mb][0], qf[j][mb][1],
                             qf[j][mb][2], qf[j][mb][3], b0[nf], b1[nf]);
        }

        // ---- mask + exp; write unnormalized attn; stage P ----
        #pragma unroll
        for (int mb = 0; mb < 2; mb++) {
            int row = wm * 32 + mb * 16 + g;
            #pragma unroll
            for (int nf = 0; nf < 2; nf++) {
                int col = wn * 16 + nf * 8 + 2 * tig;
                int2 m0 = mreg[mb][nf][0];
                int2 m1 = mreg[mb][nf][1];
                float p00 = m0.x ? __expf(acc[mb][nf][0]) : 0.f;
                float p01 = m0.y ? __expf(acc[mb][nf][1]) : 0.f;
                float p10 = m1.x ? __expf(acc[mb][nf][2]) : 0.f;
                float p11 = m1.y ? __expf(acc[mb][nf][3]) : 0.f;
                lp[mb][0] += p00 + p01;
                lp[mb][1] += p10 + p11;
                *(float2*)(attn + (size_t)(q0 + row)     * S_LEN + kt + col) = make_float2(p00, p01);
                *(float2*)(attn + (size_t)(q0 + row + 8) * S_LEN + kt + col) = make_float2(p10, p11);
                float2 s0, s1;
                s0.x = __uint_as_float(f2tf32(p00)); s0.y = __uint_as_float(f2tf32(p01));
                s1.x = __uint_as_float(f2tf32(p10)); s1.y = __uint_as_float(f2tf32(p11));
                *(float2*)&Ps[row       * PADK + col] = s0;
                *(float2*)&Ps[(row + 8) * PADK + col] = s1;
            }
        }
        __syncthreads();

        // ---- O += P V ----
        #pragma unroll
        for (int j = 0; j < 8; j++) {
            int kk = j * 8;
            uint32_t a[2][4];
            #pragma unroll
            for (int mb = 0; mb < 2; mb++) {
                int r0 = wm * 32 + mb * 16 + g;
                a[mb][0] = __float_as_uint(Ps[r0       * PADK + kk + tig]);
                a[mb][1] = __float_as_uint(Ps[(r0 + 8) * PADK + kk + tig]);
                a[mb][2] = __float_as_uint(Ps[r0       * PADK + kk + tig + 4]);
                a[mb][3] = __float_as_uint(Ps[(r0 + 8) * PADK + kk + tig + 4]);
            }
            #pragma unroll
            for (int nf = 0; nf < 2; nf++) {
                int dc = wn * 16 + nf * 8 + g;
                uint32_t b0 = f2tf32(Vc[(kk + tig)     * PADV + dc]);
                uint32_t b1 = f2tf32(Vc[(kk + tig + 4) * PADV + dc]);
                #pragma unroll
                for (int mb = 0; mb < 2; mb++)
                    mma_tf32(o[mb][nf], a[mb][0], a[mb][1], a[mb][2], a[mb][3], b0, b1);
            }
        }
    }

    // ---- row-sum reduction -> l_inv ----
    #pragma unroll
    for (int mb = 0; mb < 2; mb++)
        #pragma unroll
        for (int h = 0; h < 2; h++) {
            float s = lp[mb][h];
            s += __shfl_xor_sync(0xffffffffu, s, 1);
            s += __shfl_xor_sync(0xffffffffu, s, 2);
            lp[mb][h] = s;
        }
    if (tig == 0) {
        #pragma unroll
        for (int mb = 0; mb < 2; mb++)
            #pragma unroll
            for (int h = 0; h < 2; h++)
                red[(wm * 32 + mb * 16 + g + h * 8) * 4 + wn] = lp[mb][h];
    }
    __syncthreads();
    if (tid < 64)
        liS[tid] = 1.f / (red[tid * 4] + red[tid * 4 + 1] + red[tid * 4 + 2] + red[tid * 4 + 3]);
    __syncthreads();

    // ---- scale + write context ----
    #pragma unroll
    for (int mb = 0; mb < 2; mb++) {
        int row = wm * 32 + mb * 16 + g;
        float li0 = liS[row], li1 = liS[row + 8];
        #pragma unroll
        for (int nf = 0; nf < 2; nf++) {
            int col = wn * 16 + nf * 8 + 2 * tig;
            *(float2*)(ctx + (size_t)(q0 + row)     * D_K + col) =
                make_float2(o[mb][nf][0] * li0, o[mb][nf][1] * li0);
            *(float2*)(ctx + (size_t)(q0 + row + 8) * D_K + col) =
                make_float2(o[mb][nf][2] * li1, o[mb][nf][3] * li1);
        }
    }

    // ---- fused normalization of this block's attn strip (L2-hot) ----
    #pragma unroll 4
    for (int i = tid; i < MT * (S_LEN / 4); i += THREADS) {
        int row = i >> 9;                      // 512 float4 per row
        float li = liS[row];
        float4* p = (float4*)(attn + (size_t)(q0 + row) * S_LEN) + (i & 511);
        float4 v = *p;
        v.x *= li; v.y *= li; v.z *= li; v.w *= li;
        *p = v;
    }
}

extern "C" void kernel_launch(void* const* d_in, const int* in_sizes, int n_in,
                              void* d_out, int out_size) {
    const float* Q    = (const float*)d_in[0];
    const float* K    = (const float*)d_in[1];
    const float* V    = (const float*)d_in[2];
    const int*   mask = (const int*)d_in[3];
    float* out = (float*)d_out;

    const int smem_bytes = (2 * NT * PADK + 2 * NT * PADV + MT * PADK + 64 * 4 + 64) * sizeof(float);
    cudaFuncSetAttribute(sdpa_fwd, cudaFuncAttributeMaxDynamicSharedMemorySize, smem_bytes);

    dim3 grid(S_LEN / MT, BH);
    sdpa_fwd<<<grid, THREADS, smem_bytes>>>(Q, K, V, mask, out);
}

// round 4
// speedup vs baseline: 1.2464x; 1.2464x over previous
#include <cuda_runtime.h>
#include <cstdint>

#define S_LEN   2048
#define D_K     64
#define BH      64
#define MT      64
#define NT      64
#define PADK    68          // stride%32banks=4 -> conflict-free Q/K/P gathers
#define PADV    72          // stride%32banks=8 -> conflict-free V B-operand gathers
#define THREADS 256

__device__ float g_linv[BH * S_LEN];   // 512 KB static scratch

__device__ __forceinline__ uint32_t f2tf32(float x) {
    uint32_t r;
    asm("cvt.rna.tf32.f32 %0, %1;" : "=r"(r) : "f"(x));
    return r;
}

__device__ __forceinline__ void mma_tf32(float c[4],
                                         uint32_t a0, uint32_t a1, uint32_t a2, uint32_t a3,
                                         uint32_t b0, uint32_t b1) {
    asm volatile(
        "mma.sync.aligned.m16n8k8.row.col.f32.tf32.tf32.f32 "
        "{%0,%1,%2,%3},{%4,%5,%6,%7},{%8,%9},{%0,%1,%2,%3};"
        : "+f"(c[0]), "+f"(c[1]), "+f"(c[2]), "+f"(c[3])
        : "r"(a0), "r"(a1), "r"(a2), "r"(a3), "r"(b0), "r"(b1));
}

__device__ __forceinline__ void cp_async16(uint32_t s, const void* g) {
    asm volatile("cp.async.cg.shared.global [%0], [%1], 16;" :: "r"(s), "l"(g));
}
#define CP_COMMIT() asm volatile("cp.async.commit_group;")
#define CP_WAIT1()  asm volatile("cp.async.wait_group 1;")
#define CP_WAIT0()  asm volatile("cp.async.wait_group 0;")

__device__ __forceinline__ void cp_tile(uint32_t dst_base, const float* __restrict__ src,
                                        int tid, int pad) {
    #pragma unroll
    for (int i = 0; i < 4; i++) {
        int idx = i * THREADS + tid;
        int row = idx >> 4;
        int c4  = (idx & 15) << 2;
        cp_async16(dst_base + (row * pad + c4) * 4, src + idx * 4);
    }
}

// load Q tile: scale 1/8 folded, tf32-rounded, into padded smem
__device__ __forceinline__ void load_q(float* Qs, const float* __restrict__ Qg, int tid) {
    const float4* q4 = (const float4*)Qg;
    #pragma unroll
    for (int i = 0; i < 4; i++) {
        int idx = i * THREADS + tid;
        float4 v = q4[idx];
        int row = idx >> 4;
        int c4  = (idx & 15) << 2;
        float* d = Qs + row * PADK + c4;
        d[0] = __uint_as_float(f2tf32(v.x * 0.125f));
        d[1] = __uint_as_float(f2tf32(v.y * 0.125f));
        d[2] = __uint_as_float(f2tf32(v.z * 0.125f));
        d[3] = __uint_as_float(f2tf32(v.w * 0.125f));
    }
}

// =========================== pass 1: row sums ===========================
__global__ __launch_bounds__(THREADS, 4)
void sdpa_stats(const float* __restrict__ Q, const float* __restrict__ K,
                const int* __restrict__ mask) {
    extern __shared__ float sm[];
    float* Qs   = sm;                                  // 64 x PADK
    float* Ks[2] = { sm + MT * PADK, sm + 2 * MT * PADK };
    float* red  = sm + 3 * MT * PADK;                  // 64 x 4

    const uint32_t base = (uint32_t)__cvta_generic_to_shared(sm);
    const uint32_t KsA[2] = { base + MT * PADK * 4, base + 2 * MT * PADK * 4 };

    const int bh  = blockIdx.y;
    const int q0  = blockIdx.x * MT;
    const int tid = threadIdx.x;
    const int lane = tid & 31, wid = tid >> 5;
    const int g = lane >> 2, tig = lane & 3;
    const int wm = wid & 1, wn = wid >> 1;

    const float* Qg = Q + ((size_t)bh * S_LEN + q0) * D_K;
    const float* Kg = K + (size_t)bh * S_LEN * D_K;
    const int*   Mg = mask + (size_t)bh * S_LEN * S_LEN;

    load_q(Qs, Qg, tid);
    cp_tile(KsA[0], Kg, tid, PADK);
    CP_COMMIT();

    float lp[2][2] = {};
    int buf = 0;
    for (int kt = 0; kt < S_LEN; kt += NT, buf ^= 1) {
        __syncthreads();
        if (kt + NT < S_LEN) {
            cp_tile(KsA[buf ^ 1], Kg + (size_t)(kt + NT) * D_K, tid, PADK);
            CP_COMMIT();
            CP_WAIT1();
        } else {
            CP_WAIT0();
        }
        __syncthreads();
        const float* Kc = Ks[buf];

        // mask prefetch
        int2 mreg[2][2][2];
        #pragma unroll
        for (int mb = 0; mb < 2; mb++) {
            int row = wm * 32 + mb * 16 + g;
            #pragma unroll
            for (int nf = 0; nf < 2; nf++) {
                int col = wn * 16 + nf * 8 + 2 * tig;
                mreg[mb][nf][0] = *(const int2*)(Mg + (size_t)(q0 + row)     * S_LEN + kt + col);
                mreg[mb][nf][1] = *(const int2*)(Mg + (size_t)(q0 + row + 8) * S_LEN + kt + col);
            }
        }

        float acc[2][2][4] = {};
        #pragma unroll
        for (int j = 0; j < 8; j++) {
            int k0 = j * 8;
            uint32_t a[2][4];
            #pragma unroll
            for (int mb = 0; mb < 2; mb++) {
                int r0 = wm * 32 + mb * 16 + g;
                a[mb][0] = __float_as_uint(Qs[r0       * PADK + k0 + tig]);
                a[mb][1] = __float_as_uint(Qs[(r0 + 8) * PADK + k0 + tig]);
                a[mb][2] = __float_as_uint(Qs[r0       * PADK + k0 + tig + 4]);
                a[mb][3] = __float_as_uint(Qs[(r0 + 8) * PADK + k0 + tig + 4]);
            }
            #pragma unroll
            for (int nf = 0; nf < 2; nf++) {
                int nc = wn * 16 + nf * 8 + g;
                uint32_t b0 = f2tf32(Kc[nc * PADK + k0 + tig]);
                uint32_t b1 = f2tf32(Kc[nc * PADK + k0 + tig + 4]);
                #pragma unroll
                for (int mb = 0; mb < 2; mb++)
                    mma_tf32(acc[mb][nf], a[mb][0], a[mb][1], a[mb][2], a[mb][3], b0, b1);
            }
        }

        #pragma unroll
        for (int mb = 0; mb < 2; mb++)
            #pragma unroll
            for (int nf = 0; nf < 2; nf++) {
                int2 m0 = mreg[mb][nf][0];
                int2 m1 = mreg[mb][nf][1];
                lp[mb][0] += (m0.x ? __expf(acc[mb][nf][0]) : 0.f)
                           + (m0.y ? __expf(acc[mb][nf][1]) : 0.f);
                lp[mb][1] += (m1.x ? __expf(acc[mb][nf][2]) : 0.f)
                           + (m1.y ? __expf(acc[mb][nf][3]) : 0.f);
            }
    }

    #pragma unroll
    for (int mb = 0; mb < 2; mb++)
        #pragma unroll
        for (int h = 0; h < 2; h++) {
            float s = lp[mb][h];
            s += __shfl_xor_sync(0xffffffffu, s, 1);
            s += __shfl_xor_sync(0xffffffffu, s, 2);
            lp[mb][h] = s;
        }
    if (tig == 0)
        #pragma unroll
        for (int mb = 0; mb < 2; mb++)
            #pragma unroll
            for (int h = 0; h < 2; h++)
                red[(wm * 32 + mb * 16 + g + h * 8) * 4 + wn] = lp[mb][h];
    __syncthreads();
    if (tid < 64)
        g_linv[(size_t)bh * S_LEN + q0 + tid] =
            1.f / (red[tid * 4] + red[tid * 4 + 1] + red[tid * 4 + 2] + red[tid * 4 + 3]);
}

// ================= pass 2: recompute, write normalized attn, PV =================
__global__ __launch_bounds__(THREADS, 3)
void sdpa_emit(const float* __restrict__ Q, const float* __restrict__ K,
               const float* __restrict__ V, const int* __restrict__ mask,
               float* __restrict__ out) {
    extern __shared__ float sm[];
    float* Qs = sm;                        // 64 x PADK
    float* Ks = Qs + MT * PADK;            // 64 x PADK
    float* Vs = Ks + MT * PADK;            // 64 x PADV
    float* Ps = Vs + MT * PADV;            // 64 x PADK

    const uint32_t base = (uint32_t)__cvta_generic_to_shared(sm);
    const uint32_t KsA = base + MT * PADK * 4;
    const uint32_t VsA = KsA + MT * PADK * 4;

    const int bh  = blockIdx.y;
    const int q0  = blockIdx.x * MT;
    const int tid = threadIdx.x;
    const int lane = tid & 31, wid = tid >> 5;
    const int g = lane >> 2, tig = lane & 3;
    const int wm = wid & 1, wn = wid >> 1;

    const float* Qg = Q + ((size_t)bh * S_LEN + q0) * D_K;
    const float* Kg = K + (size_t)bh * S_LEN * D_K;
    const float* Vg = V + (size_t)bh * S_LEN * D_K;
    const int*   Mg = mask + (size_t)bh * S_LEN * S_LEN;
    float* ctx  = out + (size_t)bh * S_LEN * D_K;
    float* attn = out + (size_t)BH * S_LEN * D_K + (size_t)bh * S_LEN * S_LEN;

    // per-thread l_inv for owned rows
    const float* lig = g_linv + (size_t)bh * S_LEN + q0;
    float li[2][2];
    #pragma unroll
    for (int mb = 0; mb < 2; mb++) {
        int row = wm * 32 + mb * 16 + g;
        li[mb][0] = lig[row];
        li[mb][1] = lig[row + 8];
    }

    load_q(Qs, Qg, tid);
    cp_tile(KsA, Kg, tid, PADK);           // K(0)
    CP_COMMIT();

    float o[2][2][4] = {};

    for (int kt = 0; kt < S_LEN; kt += NT) {
        CP_WAIT0();                        // K(t) arrived
        __syncthreads();                   // K visible; prev PV done (Vs free)

        cp_tile(VsA, Vg + (size_t)kt * D_K, tid, PADV);   // V(t)
        CP_COMMIT();

        // mask prefetch (overlaps QK)
        int2 mreg[2][2][2];
        #pragma unroll
        for (int mb = 0; mb < 2; mb++) {
            int row = wm * 32 + mb * 16 + g;
            #pragma unroll
            for (int nf = 0; nf < 2; nf++) {
                int col = wn * 16 + nf * 8 + 2 * tig;
                mreg[mb][nf][0] = *(const int2*)(Mg + (size_t)(q0 + row)     * S_LEN + kt + col);
                mreg[mb][nf][1] = *(const int2*)(Mg + (size_t)(q0 + row + 8) * S_LEN + kt + col);
            }
        }

        // ---- S = Q K^T ----
        float acc[2][2][4] = {};
        #pragma unroll
        for (int j = 0; j < 8; j++) {
            int k0 = j * 8;
            uint32_t a[2][4];
            #pragma unroll
            for (int mb = 0; mb < 2; mb++) {
                int r0 = wm * 32 + mb * 16 + g;
                a[mb][0] = __float_as_uint(Qs[r0       * PADK + k0 + tig]);
                a[mb][1] = __float_as_uint(Qs[(r0 + 8) * PADK + k0 + tig]);
                a[mb][2] = __float_as_uint(Qs[r0       * PADK + k0 + tig + 4]);
                a[mb][3] = __float_as_uint(Qs[(r0 + 8) * PADK + k0 + tig + 4]);
            }
            #pragma unroll
            for (int nf = 0; nf < 2; nf++) {
                int nc = wn * 16 + nf * 8 + g;
                uint32_t b0 = f2tf32(Ks[nc * PADK + k0 + tig]);
                uint32_t b1 = f2tf32(Ks[nc * PADK + k0 + tig + 4]);
                #pragma unroll
                for (int mb = 0; mb < 2; mb++)
                    mma_tf32(acc[mb][nf], a[mb][0], a[mb][1], a[mb][2], a[mb][3], b0, b1);
            }
        }
        __syncthreads();                   // all warps done reading Ks

        // prefetch K(t+1) into Ks (hidden behind exp/attn-write/PV)
        const float* Knext = (kt + NT < S_LEN) ? Kg + (size_t)(kt + NT) * D_K : Kg;
        cp_tile(KsA, Knext, tid, PADK);
        CP_COMMIT();

        // ---- normalized p: write attn, stage P ----
        #pragma unroll
        for (int mb = 0; mb < 2; mb++) {
            int row = wm * 32 + mb * 16 + g;
            #pragma unroll
            for (int nf = 0; nf < 2; nf++) {
                int col = wn * 16 + nf * 8 + 2 * tig;
                int2 m0 = mreg[mb][nf][0];
                int2 m1 = mreg[mb][nf][1];
                float p00 = m0.x ? __expf(acc[mb][nf][0]) * li[mb][0] : 0.f;
                float p01 = m0.y ? __expf(acc[mb][nf][1]) * li[mb][0] : 0.f;
                float p10 = m1.x ? __expf(acc[mb][nf][2]) * li[mb][1] : 0.f;
                float p11 = m1.y ? __expf(acc[mb][nf][3]) * li[mb][1] : 0.f;
                *(float2*)(attn + (size_t)(q0 + row)     * S_LEN + kt + col) = make_float2(p00, p01);
                *(float2*)(attn + (size_t)(q0 + row + 8) * S_LEN + kt + col) = make_float2(p10, p11);
                float2 s0, s1;
                s0.x = __uint_as_float(f2tf32(p00)); s0.y = __uint_as_float(f2tf32(p01));
                s1.x = __uint_as_float(f2tf32(p10)); s1.y = __uint_as_float(f2tf32(p11));
                *(float2*)&Ps[row       * PADK + col] = s0;
                *(float2*)&Ps[(row + 8) * PADK + col] = s1;
            }
        }

        CP_WAIT1();                        // V(t) done (K(t+1) may be in flight)
        __syncthreads();                   // Ps + Vs visible

        // ---- O += P V (P already normalized) ----
        #pragma unroll
        for (int j = 0; j < 8; j++) {
            int kk = j * 8;
            uint32_t a[2][4];
            #pragma unroll
            for (int mb = 0; mb < 2; mb++) {
                int r0 = wm * 32 + mb * 16 + g;
                a[mb][0] = __float_as_uint(Ps[r0       * PADK + kk + tig]);
                a[mb][1] = __float_as_uint(Ps[(r0 + 8) * PADK + kk + tig]);
                a[mb][2] = __float_as_uint(Ps[r0       * PADK + kk + tig + 4]);
                a[mb][3] = __float_as_uint(Ps[(r0 + 8) * PADK + kk + tig + 4]);
            }
            #pragma unroll
            for (int nf = 0; nf < 2; nf++) {
                int dc = wn * 16 + nf * 8 + g;
                uint32_t b0 = f2tf32(Vs[(kk + tig)     * PADV + dc]);
                uint32_t b1 = f2tf32(Vs[(kk + tig + 4) * PADV + dc]);
                #pragma unroll
                for (int mb = 0; mb < 2; mb++)
                    mma_tf32(o[mb][nf], a[mb][0], a[mb][1], a[mb][2], a[mb][3], b0, b1);
            }
        }
    }

    // ---- write context (already normalized) ----
    #pragma unroll
    for (int mb = 0; mb < 2; mb++) {
        int row = wm * 32 + mb * 16 + g;
        #pragma unroll
        for (int nf = 0; nf < 2; nf++) {
            int col = wn * 16 + nf * 8 + 2 * tig;
            *(float2*)(ctx + (size_t)(q0 + row)     * D_K + col) =
                make_float2(o[mb][nf][0], o[mb][nf][1]);
            *(float2*)(ctx + (size_t)(q0 + row + 8) * D_K + col) =
                make_float2(o[mb][nf][2], o[mb][nf][3]);
        }
    }
}

extern "C" void kernel_launch(void* const* d_in, const int* in_sizes, int n_in,
                              void* d_out, int out_size) {
    const float* Q    = (const float*)d_in[0];
    const float* K    = (const float*)d_in[1];
    const float* V    = (const float*)d_in[2];
    const int*   mask = (const int*)d_in[3];
    float* out = (float*)d_out;

    const int smem1 = (3 * MT * PADK + 64 * 4) * sizeof(float);               // 53.2 KB
    const int smem2 = (3 * MT * PADK + MT * PADV) * sizeof(float);            // 70.7 KB
    cudaFuncSetAttribute(sdpa_stats, cudaFuncAttributeMaxDynamicSharedMemorySize, smem1);
    cudaFuncSetAttribute(sdpa_emit,  cudaFuncAttributeMaxDynamicSharedMemorySize, smem2);

    dim3 grid(S_LEN / MT, BH);
    sdpa_stats<<<grid, THREADS, smem1>>>(Q, K, mask);
    sdpa_emit <<<grid, THREADS, smem2>>>(Q, K, V, mask, out);
}

// round 5
// speedup vs baseline: 1.5080x; 1.2098x over previous
#include <cuda_runtime.h>
#include <cstdint>

#define S_LEN   2048
#define D_K     64
#define BH      64
#define MT      64
#define NT      64
#define PADK    68
#define PADV    72
#define THREADS 256
#define NBLOCKS (BH * (S_LEN / MT))   // 2048

__device__ float g_linv[BH * S_LEN];
__device__ int   g_queue[NBLOCKS];
__device__ int   g_push;
__device__ int   g_ticket;

__device__ __forceinline__ uint32_t f2tf32(float x) {
    uint32_t r;
    asm("cvt.rna.tf32.f32 %0, %1;" : "=r"(r) : "f"(x));
    return r;
}

__device__ __forceinline__ void mma_tf32(float c[4],
                                         uint32_t a0, uint32_t a1, uint32_t a2, uint32_t a3,
                                         uint32_t b0, uint32_t b1) {
    asm volatile(
        "mma.sync.aligned.m16n8k8.row.col.f32.tf32.tf32.f32 "
        "{%0,%1,%2,%3},{%4,%5,%6,%7},{%8,%9},{%0,%1,%2,%3};"
        : "+f"(c[0]), "+f"(c[1]), "+f"(c[2]), "+f"(c[3])
        : "r"(a0), "r"(a1), "r"(a2), "r"(a3), "r"(b0), "r"(b1));
}

__device__ __forceinline__ void cp_async16(uint32_t s, const void* g) {
    asm volatile("cp.async.cg.shared.global [%0], [%1], 16;" :: "r"(s), "l"(g));
}
#define CP_COMMIT() asm volatile("cp.async.commit_group;")
#define CP_WAIT1()  asm volatile("cp.async.wait_group 1;")
#define CP_WAIT0()  asm volatile("cp.async.wait_group 0;")

__device__ __forceinline__ void cp_tile(uint32_t dst_base, const float* __restrict__ src,
                                        int tid, int pad) {
    #pragma unroll
    for (int i = 0; i < 4; i++) {
        int idx = i * THREADS + tid;
        int row = idx >> 4;
        int c4  = (idx & 15) << 2;
        cp_async16(dst_base + (row * pad + c4) * 4, src + idx * 4);
    }
}

__device__ __forceinline__ void load_q(float* Qs, const float* __restrict__ Qg, int tid) {
    const float4* q4 = (const float4*)Qg;
    #pragma unroll
    for (int i = 0; i < 4; i++) {
        int idx = i * THREADS + tid;
        float4 v = q4[idx];
        int row = idx >> 4;
        int c4  = (idx & 15) << 2;
        float* d = Qs + row * PADK + c4;
        d[0] = __uint_as_float(f2tf32(v.x * 0.125f));
        d[1] = __uint_as_float(f2tf32(v.y * 0.125f));
        d[2] = __uint_as_float(f2tf32(v.z * 0.125f));
        d[3] = __uint_as_float(f2tf32(v.w * 0.125f));
    }
}

__global__ __launch_bounds__(THREADS, 3)
void sdpa_fused(const float* __restrict__ Q, const float* __restrict__ K,
                const float* __restrict__ V, const int* __restrict__ mask,
                float* __restrict__ out) {
    extern __shared__ float sm[];
    float* Qs  = sm;                        // 64 x PADK
    float* Ks  = Qs + MT * PADK;            // 64 x PADK
    float* Vs  = Ks + MT * PADK;            // 64 x PADV
    float* Ps  = Vs + MT * PADV;            // 64 x PADK
    float* red = Ps + MT * PADK;            // 64 x 4
    float* liS = red + 64 * 4;              // 64
    __shared__ int s_strip;

    const uint32_t base = (uint32_t)__cvta_generic_to_shared(sm);
    const uint32_t KsA = base + MT * PADK * 4;
    const uint32_t VsA = KsA + MT * PADK * 4;

    const int bh  = blockIdx.y;
    const int q0  = blockIdx.x * MT;
    const int myid = blockIdx.y * gridDim.x + blockIdx.x;
    const int tid = threadIdx.x;
    const int lane = tid & 31, wid = tid >> 5;
    const int g = lane >> 2, tig = lane & 3;
    const int wm = wid & 1, wn = wid >> 1;

    const float* Qg = Q + ((size_t)bh * S_LEN + q0) * D_K;
    const float* Kg = K + (size_t)bh * S_LEN * D_K;
    const float* Vg = V + (size_t)bh * S_LEN * D_K;
    const int*   Mg = mask + (size_t)bh * S_LEN * S_LEN;
    float* ctx  = out + (size_t)bh * S_LEN * D_K;
    float* attn_base = out + (size_t)BH * S_LEN * D_K;
    float* attn = attn_base + (size_t)bh * S_LEN * S_LEN;

    load_q(Qs, Qg, tid);
    cp_tile(KsA, Kg, tid, PADK);           // K(0)
    CP_COMMIT();

    float o[2][2][4] = {};
    float lp[2][2] = {};

    for (int kt = 0; kt < S_LEN; kt += NT) {
        CP_WAIT0();                        // K(t) arrived
        __syncthreads();                   // K visible; prev PV done (Vs free)

        cp_tile(VsA, Vg + (size_t)kt * D_K, tid, PADV);   // V(t)
        CP_COMMIT();

        // mask prefetch (overlaps QK)
        int2 mreg[2][2][2];
        #pragma unroll
        for (int mb = 0; mb < 2; mb++) {
            int row = wm * 32 + mb * 16 + g;
            #pragma unroll
            for (int nf = 0; nf < 2; nf++) {
                int col = wn * 16 + nf * 8 + 2 * tig;
                mreg[mb][nf][0] = *(const int2*)(Mg + (size_t)(q0 + row)     * S_LEN + kt + col);
                mreg[mb][nf][1] = *(const int2*)(Mg + (size_t)(q0 + row + 8) * S_LEN + kt + col);
            }
        }

        // ---- S = Q K^T ----
        float acc[2][2][4] = {};
        #pragma unroll
        for (int j = 0; j < 8; j++) {
            int k0 = j * 8;
            uint32_t a[2][4];
            #pragma unroll
            for (int mb = 0; mb < 2; mb++) {
                int r0 = wm * 32 + mb * 16 + g;
                a[mb][0] = __float_as_uint(Qs[r0       * PADK + k0 + tig]);
                a[mb][1] = __float_as_uint(Qs[(r0 + 8) * PADK + k0 + tig]);
                a[mb][2] = __float_as_uint(Qs[r0       * PADK + k0 + tig + 4]);
                a[mb][3] = __float_as_uint(Qs[(r0 + 8) * PADK + k0 + tig + 4]);
            }
            #pragma unroll
            for (int nf = 0; nf < 2; nf++) {
                int nc = wn * 16 + nf * 8 + g;
                uint32_t b0 = f2tf32(Ks[nc * PADK + k0 + tig]);
                uint32_t b1 = f2tf32(Ks[nc * PADK + k0 + tig + 4]);
                #pragma unroll
                for (int mb = 0; mb < 2; mb++)
                    mma_tf32(acc[mb][nf], a[mb][0], a[mb][1], a[mb][2], a[mb][3], b0, b1);
            }
        }
        __syncthreads();                   // all warps done reading Ks

        // prefetch K(t+1) (hidden behind exp/attn-write/PV)
        const float* Knext = (kt + NT < S_LEN) ? Kg + (size_t)(kt + NT) * D_K : Kg;
        cp_tile(KsA, Knext, tid, PADK);
        CP_COMMIT();

        // ---- unnormalized p = mask * exp(s): write attn, stage P, sum rows ----
        #pragma unroll
        for (int mb = 0; mb < 2; mb++) {
            int row = wm * 32 + mb * 16 + g;
            #pragma unroll
            for (int nf = 0; nf < 2; nf++) {
                int col = wn * 16 + nf * 8 + 2 * tig;
                int2 m0 = mreg[mb][nf][0];
                int2 m1 = mreg[mb][nf][1];
                float p00 = m0.x ? __expf(acc[mb][nf][0]) : 0.f;
                float p01 = m0.y ? __expf(acc[mb][nf][1]) : 0.f;
                float p10 = m1.x ? __expf(acc[mb][nf][2]) : 0.f;
                float p11 = m1.y ? __expf(acc[mb][nf][3]) : 0.f;
                lp[mb][0] += p00 + p01;
                lp[mb][1] += p10 + p11;
                *(float2*)(attn + (size_t)(q0 + row)     * S_LEN + kt + col) = make_float2(p00, p01);
                *(float2*)(attn + (size_t)(q0 + row + 8) * S_LEN + kt + col) = make_float2(p10, p11);
                float2 s0, s1;
                s0.x = __uint_as_float(f2tf32(p00)); s0.y = __uint_as_float(f2tf32(p01));
                s1.x = __uint_as_float(f2tf32(p10)); s1.y = __uint_as_float(f2tf32(p11));
                *(float2*)&Ps[row       * PADK + col] = s0;
                *(float2*)&Ps[(row + 8) * PADK + col] = s1;
            }
        }

        CP_WAIT1();                        // V(t) done (K(t+1) still in flight)
        __syncthreads();                   // Ps + Vs visible

        // ---- O += P V (unnormalized) ----
        #pragma unroll
        for (int j = 0; j < 8; j++) {
            int kk = j * 8;
            uint32_t a[2][4];
            #pragma unroll
            for (int mb = 0; mb < 2; mb++) {
                int r0 = wm * 32 + mb * 16 + g;
                a[mb][0] = __float_as_uint(Ps[r0       * PADK + kk + tig]);
                a[mb][1] = __float_as_uint(Ps[(r0 + 8) * PADK + kk + tig]);
                a[mb][2] = __float_as_uint(Ps[r0       * PADK + kk + tig + 4]);
                a[mb][3] = __float_as_uint(Ps[(r0 + 8) * PADK + kk + tig + 4]);
            }
            #pragma unroll
            for (int nf = 0; nf < 2; nf++) {
                int dc = wn * 16 + nf * 8 + g;
                uint32_t b0 = f2tf32(Vs[(kk + tig)     * PADV + dc]);
                uint32_t b1 = f2tf32(Vs[(kk + tig + 4) * PADV + dc]);
                #pragma unroll
                for (int mb = 0; mb < 2; mb++)
                    mma_tf32(o[mb][nf], a[mb][0], a[mb][1], a[mb][2], a[mb][3], b0, b1);
            }
        }
    }

    // ---- row sums -> l_inv (smem + gmem) ----
    #pragma unroll
    for (int mb = 0; mb < 2; mb++)
        #pragma unroll
        for (int h = 0; h < 2; h++) {
            float s = lp[mb][h];
            s += __shfl_xor_sync(0xffffffffu, s, 1);
            s += __shfl_xor_sync(0xffffffffu, s, 2);
            lp[mb][h] = s;
        }
    if (tig == 0)
        #pragma unroll
        for (int mb = 0; mb < 2; mb++)
            #pragma unroll
            for (int h = 0; h < 2; h++)
                red[(wm * 32 + mb * 16 + g + h * 8) * 4 + wn] = lp[mb][h];
    __syncthreads();
    if (tid < 64) {
        float li = 1.f / (red[tid * 4] + red[tid * 4 + 1] + red[tid * 4 + 2] + red[tid * 4 + 3]);
        liS[tid] = li;
        g_linv[(size_t)bh * S_LEN + q0 + tid] = li;
    }
    __syncthreads();

    // ---- write context (scale by own l_inv) ----
    #pragma unroll
    for (int mb = 0; mb < 2; mb++) {
        int row = wm * 32 + mb * 16 + g;
        float li0 = liS[row], li1 = liS[row + 8];
        #pragma unroll
        for (int nf = 0; nf < 2; nf++) {
            int col = wn * 16 + nf * 8 + 2 * tig;
            *(float2*)(ctx + (size_t)(q0 + row)     * D_K + col) =
                make_float2(o[mb][nf][0] * li0, o[mb][nf][1] * li0);
            *(float2*)(ctx + (size_t)(q0 + row + 8) * D_K + col) =
                make_float2(o[mb][nf][2] * li1, o[mb][nf][3] * li1);
        }
    }

    // ---- produce/consume: normalize one already-produced strip ----
    __threadfence();                       // all threads: attn strip + g_linv visible
    __syncthreads();
    if (tid == 0) {
        int idx = atomicAdd(&g_push, 1);
        asm volatile("st.release.gpu.global.s32 [%0], %1;"
                     :: "l"(g_queue + idx), "r"(myid) : "memory");
        int t = atomicAdd(&g_ticket, 1);
        int s;
        while (true) {
            asm volatile("ld.acquire.gpu.global.s32 %0, [%1];"
                         : "=r"(s) : "l"(g_queue + t) : "memory");
            if (s >= 0) break;
            __nanosleep(64);
        }
        s_strip = s;
    }
    __syncthreads();

    const int sid  = s_strip;
    const int sbh  = sid >> 5;
    const int sq0  = (sid & 31) * MT;
    float* sattn = attn_base + (size_t)sbh * S_LEN * S_LEN + (size_t)sq0 * S_LEN;
    if (tid < 64) liS[tid] = g_linv[(size_t)sbh * S_LEN + sq0 + tid];
    __syncthreads();

    #pragma unroll 4
    for (int i = tid; i < MT * (S_LEN / 4); i += THREADS) {
        float li = liS[i >> 9];
        float4* p = (float4*)sattn + i;
        float4 v = *p;
        v.x *= li; v.y *= li; v.z *= li; v.w *= li;
        *p = v;
    }
}

extern "C" void kernel_launch(void* const* d_in, const int* in_sizes, int n_in,
                              void* d_out, int out_size) {
    const float* Q    = (const float*)d_in[0];
    const float* K    = (const float*)d_in[1];
    const float* V    = (const float*)d_in[2];
    const int*   mask = (const int*)d_in[3];
    float* out = (float*)d_out;

    // reset queue/counters (graph-capturable memset nodes)
    void* addr;
    cudaGetSymbolAddress(&addr, g_queue);
    cudaMemsetAsync(addr, 0xFF, sizeof(int) * NBLOCKS);
    cudaGetSymbolAddress(&addr, g_push);
    cudaMemsetAsync(addr, 0, sizeof(int));
    cudaGetSymbolAddress(&addr, g_ticket);
    cudaMemsetAsync(addr, 0, sizeof(int));

    const int smem = (3 * MT * PADK + MT * PADV + 64 * 4 + 64) * sizeof(float);  // ~72 KB
    cudaFuncSetAttribute(sdpa_fused, cudaFuncAttributeMaxDynamicSharedMemorySize, smem);

    dim3 grid(S_LEN / MT, BH);
    sdpa_fused<<<grid, THREADS, smem>>>(Q, K, V, mask, out);
}